// round 7
// baseline (speedup 1.0000x reference)
#include <cuda_runtime.h>
#include <cuda_bf16.h>
#include <math.h>
#include <cstdint>

#define PB 8
#define PN 1024
#define PC 768
#define PH 8
#define PD 96
#define PM 1024

// bf16 hi/lo operand arrays (split done once by producers)
__device__ __nv_bfloat16 g_qh[(size_t)PB*PN*PC], g_ql[(size_t)PB*PN*PC];
__device__ __nv_bfloat16 g_kh[(size_t)PB*PN*PC], g_kl[(size_t)PB*PN*PC];
__device__ float         g_v [(size_t)PB*PN*PC];
__device__ float         g_S [(size_t)PB*PH*PN*PM];        // fp32 scores (qk -> softmax)
__device__ __nv_bfloat16 g_ph[(size_t)PB*PH*PN*PM];        // mixed attn hi
__device__ __nv_bfloat16 g_pl[(size_t)PB*PH*PN*PM];        // mixed attn lo
__device__ __nv_bfloat16 g_vth[(size_t)PB*PH*PD*PM], g_vtl[(size_t)PB*PH*PD*PM]; // V^T
__device__ float         g_vsum[PB*PH*PD];                  // colsum of V per (bg,d)
__device__ __nv_bfloat16 g_ohh[(size_t)PB*PN*PC], g_ohl[(size_t)PB*PN*PC];       // oh (b,n,c)
__device__ __nv_bfloat16 g_pwh[(size_t)PC*PC], g_pwl[(size_t)PC*PC];
__device__ double g_stats[16];
__device__ float  g_norm[16];

// ============================ helpers ======================================
__device__ __forceinline__ uint32_t smem_u32(const void* p) {
    uint32_t a;
    asm("{ .reg .u64 t; cvta.to.shared.u64 t, %1; cvt.u32.u64 %0, t; }"
        : "=r"(a) : "l"(p));
    return a;
}
__device__ __forceinline__ void ldsm4(uint32_t addr, uint32_t* r) {
    asm volatile("ldmatrix.sync.aligned.m8n8.x4.shared.b16 {%0,%1,%2,%3}, [%4];"
                 : "=r"(r[0]), "=r"(r[1]), "=r"(r[2]), "=r"(r[3]) : "r"(addr));
}
__device__ __forceinline__ void mma16816(float* d, const uint32_t* a, const uint32_t* b) {
    asm volatile("mma.sync.aligned.m16n8k16.row.col.f32.bf16.bf16.f32 "
                 "{%0,%1,%2,%3}, {%4,%5,%6,%7}, {%8,%9}, {%0,%1,%2,%3};"
                 : "+f"(d[0]), "+f"(d[1]), "+f"(d[2]), "+f"(d[3])
                 : "r"(a[0]), "r"(a[1]), "r"(a[2]), "r"(a[3]), "r"(b[0]), "r"(b[1]));
}
#define CP16(dst, src) asm volatile("cp.async.cg.shared.global [%0], [%1], 16;" :: "r"(dst), "l"(src))
#define CP_COMMIT()    asm volatile("cp.async.commit_group;")
#define CP_WAIT0()     asm volatile("cp.async.wait_group 0;" ::: "memory")
#define CP_WAIT1()     asm volatile("cp.async.wait_group 1;" ::: "memory")

__device__ __forceinline__ void split2(float x, float y, uint32_t& hi, uint32_t& lo) {
    __nv_bfloat16 hx = __float2bfloat16_rn(x), hy = __float2bfloat16_rn(y);
    __nv_bfloat16 lx = __float2bfloat16_rn(x - __bfloat162float(hx));
    __nv_bfloat16 ly = __float2bfloat16_rn(y - __bfloat162float(hy));
    hi = (uint32_t)__bfloat16_as_ushort(hx) | ((uint32_t)__bfloat16_as_ushort(hy) << 16);
    lo = (uint32_t)__bfloat16_as_ushort(lx) | ((uint32_t)__bfloat16_as_ushort(ly) << 16);
}
__device__ __forceinline__ void split1(float x, __nv_bfloat16& h, __nv_bfloat16& l) {
    h = __float2bfloat16_rn(x);
    l = __float2bfloat16_rn(x - __bfloat162float(h));
}
// reconstruct 4 floats from packed hi/lo bf16x2 pairs
__device__ __forceinline__ float4 rec4(uint2 h, uint2 l) {
    float4 f;
    f.x = __uint_as_float((h.x & 0xFFFFu) << 16) + __uint_as_float((l.x & 0xFFFFu) << 16);
    f.y = __uint_as_float(h.x & 0xFFFF0000u)     + __uint_as_float(l.x & 0xFFFF0000u);
    f.z = __uint_as_float((h.y & 0xFFFFu) << 16) + __uint_as_float((l.y & 0xFFFFu) << 16);
    f.w = __uint_as_float(h.y & 0xFFFF0000u)     + __uint_as_float(l.y & 0xFFFF0000u);
    return f;
}

// ---------------------------------------------------------------------------
__global__ void zero_stats_kernel() {
    int tid = threadIdx.x;
    if (tid < 16) g_stats[tid] = 0.0;
    for (int i = tid; i < PB * PH * PD; i += 256) g_vsum[i] = 0.f;
}

// ---------------------------------------------------------------------------
// Per-token 3x3 SAME convs; writes q(scaled)/k as bf16 hi/lo, v as fp32.
__global__ void conv_qkv_kernel(const float* __restrict__ x,
                                const float* __restrict__ wq,
                                const float* __restrict__ wk,
                                const float* __restrict__ wv) {
    __shared__ float simg[3][16][16];
    __shared__ float sw[3][81];
    int img = blockIdx.x;
    int tid = threadIdx.x;
    for (int e = tid; e < 768; e += 256)
        ((float*)simg)[e] = x[(size_t)img * 768 + e];
    if (tid < 81) { sw[0][tid] = wq[tid]; sw[1][tid] = wk[tid]; sw[2][tid] = wv[tid]; }
    __syncthreads();
    int i = tid >> 4, j = tid & 15;
    float out[3][3];
    #pragma unroll
    for (int a = 0; a < 3; a++)
        #pragma unroll
        for (int c = 0; c < 3; c++) out[a][c] = 0.f;
    #pragma unroll
    for (int ci = 0; ci < 3; ci++)
        #pragma unroll
        for (int di = 0; di < 3; di++) {
            int ii = i + di - 1;
            if (ii < 0 || ii > 15) continue;
            #pragma unroll
            for (int dj = 0; dj < 3; dj++) {
                int jj = j + dj - 1;
                if (jj < 0 || jj > 15) continue;
                float pix = simg[ci][ii][jj];
                int wi = ci * 9 + di * 3 + dj;
                #pragma unroll
                for (int co = 0; co < 3; co++) {
                    out[0][co] += pix * sw[0][co * 27 + wi];
                    out[1][co] += pix * sw[1][co * 27 + wi];
                    out[2][co] += pix * sw[2][co * 27 + wi];
                }
            }
        }
    const float scale = 0.10206207261596577f;  // 96^-0.5 (folded into q)
    #pragma unroll
    for (int co = 0; co < 3; co++) {
        int c = co * 256 + i * 16 + j;
        size_t o = (size_t)img * 768 + c;
        __nv_bfloat16 h, l;
        split1(out[0][co] * scale, h, l);
        g_qh[o] = h; g_ql[o] = l;
        split1(out[1][co], h, l);
        g_kh[o] = h; g_kl[o] = l;
        g_v[o] = out[2][co];
    }
}

// ---------------------------------------------------------------------------
// V transpose: v (b,m,c) fp32 -> vt hi/lo [(bg), d, m] bf16 + colsums.
__global__ void vt_kernel() {
    __shared__ float sm[64 * 97];
    __shared__ float svs[96];
    int tid = threadIdx.x;
    int mc = blockIdx.x, bg = blockIdx.y;
    int b = bg >> 3, g = bg & 7;
    int m0 = mc * 64;
    if (tid < 96) svs[tid] = 0.f;
    #pragma unroll
    for (int i = 0; i < 6; i++) {
        int idx = tid + i * 256;
        int mr = idx / 24, d4 = (idx % 24) * 4;
        float4 f = *(const float4*)&g_v[(size_t)(b * 1024 + m0 + mr) * PC + g * PD + d4];
        sm[mr * 97 + d4 + 0] = f.x;
        sm[mr * 97 + d4 + 1] = f.y;
        sm[mr * 97 + d4 + 2] = f.z;
        sm[mr * 97 + d4 + 3] = f.w;
    }
    __syncthreads();
    #pragma unroll
    for (int i = 0; i < 12; i++) {
        int idx = tid + i * 256;
        int d = idx >> 5, m2 = idx & 31;
        float v0 = sm[(2 * m2) * 97 + d];
        float v1 = sm[(2 * m2 + 1) * 97 + d];
        uint32_t h, l;
        split2(v0, v1, h, l);
        size_t o = (size_t)bg * PD * PM + (size_t)d * PM + m0 + 2 * m2;
        *(uint32_t*)&g_vth[o] = h;
        *(uint32_t*)&g_vtl[o] = l;
        atomicAdd(&svs[d], v0 + v1);
    }
    __syncthreads();
    if (tid < 96) atomicAdd(&g_vsum[bg * 96 + tid], svs[tid]);
}

// ---------------------------------------------------------------------------
// proj weight split
__global__ void pw_split_kernel(const float* __restrict__ pw) {
    int idx = blockIdx.x * 256 + threadIdx.x;      // one float4 per thread
    float4 f = *(const float4*)&pw[(size_t)idx * 4];
    uint32_t h0, l0, h1, l1;
    split2(f.x, f.y, h0, l0);
    split2(f.z, f.w, h1, l1);
    *(uint2*)&g_pwh[(size_t)idx * 4] = make_uint2(h0, h1);
    *(uint2*)&g_pwl[(size_t)idx * 4] = make_uint2(l0, l1);
}

// ===========================================================================
// qk: 128x128 tile, K=96, pure cp.async staging, 2 CTAs/SM.
// ===========================================================================
#define QK_SA 104
#define QK_TILE (128 * QK_SA * 2)         // 26624
#define QK_SMEM (4 * QK_TILE)             // 106496

__global__ void __launch_bounds__(256, 2) qk_mma_kernel() {
    extern __shared__ char smem[];
    uint32_t sb = smem_u32(smem);
    uint32_t uAHI = sb, uALO = sb + QK_TILE, uBHI = sb + 2 * QK_TILE, uBLO = sb + 3 * QK_TILE;
    int tid = threadIdx.x, wid = tid >> 5, lane = tid & 31;
    int mt = blockIdx.x, nt = blockIdx.y, bh = blockIdx.z;
    int b = bh >> 3, h = bh & 7;
    int n0 = nt * 128, m0 = mt * 128;

    // stage: 128 rows x 12 x 16B per tile, 4 tiles
    #pragma unroll
    for (int i = 0; i < 6; i++) {
        int idx = tid + i * 256;
        int row = idx / 12, c = idx % 12;
        uint32_t so = (uint32_t)(row * QK_SA) * 2 + c * 16;
        size_t qa = (size_t)(b * 1024 + n0 + row) * PC + h * PD + c * 8;
        size_t ka = (size_t)(b * 1024 + m0 + row) * PC + h * PD + c * 8;
        CP16(uAHI + so, g_qh + qa);
        CP16(uALO + so, g_ql + qa);
        CP16(uBHI + so, g_kh + ka);
        CP16(uBLO + so, g_kl + ka);
    }
    CP_COMMIT();
    CP_WAIT0();
    __syncthreads();

    int lr = lane & 7;
    int a_row = lr + ((lane >> 3) & 1) * 8, a_k = (lane >> 4) * 8;
    int b_row = lr + (lane >> 4) * 8,       b_k = ((lane >> 3) & 1) * 8;
    int wr = (wid >> 1) * 32, wc = (wid & 1) * 64;

    float acc[2][8][4] = {};
    #pragma unroll
    for (int ks = 0; ks < 6; ks++) {
        int k0 = ks * 16;
        uint32_t ah[2][4], al[2][4];
        #pragma unroll
        for (int mf = 0; mf < 2; mf++) {
            uint32_t off = (uint32_t)((wr + mf * 16 + a_row) * QK_SA + k0 + a_k) * 2;
            ldsm4(uAHI + off, ah[mf]);
            ldsm4(uALO + off, al[mf]);
        }
        #pragma unroll
        for (int np = 0; np < 4; np++) {
            uint32_t off = (uint32_t)((wc + np * 16 + b_row) * QK_SA + k0 + b_k) * 2;
            uint32_t bh4[4], bl4[4];
            ldsm4(uBHI + off, bh4);
            ldsm4(uBLO + off, bl4);
            #pragma unroll
            for (int mf = 0; mf < 2; mf++)
                #pragma unroll
                for (int sub = 0; sub < 2; sub++) {
                    float* d = acc[mf][np * 2 + sub];
                    mma16816(d, ah[mf], &bh4[sub * 2]);
                    mma16816(d, ah[mf], &bl4[sub * 2]);
                    mma16816(d, al[mf], &bh4[sub * 2]);
                }
        }
    }

    float* Sb = g_S + ((size_t)bh * PN + n0) * PM + m0;
    int r0 = wr + (lane >> 2);
    int cbase = wc + 2 * (lane & 3);
    #pragma unroll
    for (int mf = 0; mf < 2; mf++)
        #pragma unroll
        for (int nf = 0; nf < 8; nf++) {
            int rr = r0 + mf * 16, cc = cbase + nf * 8;
            *(float2*)&Sb[(size_t)rr * PM + cc]       = make_float2(acc[mf][nf][0], acc[mf][nf][1]);
            *(float2*)&Sb[(size_t)(rr + 8) * PM + cc] = make_float2(acc[mf][nf][2], acc[mf][nf][3]);
        }
}

// ---------------------------------------------------------------------------
// softmax + head-mix + BN stats; writes mixed attn as bf16 hi/lo.
__global__ void __launch_bounds__(256) softmax_mix_kernel(const float* __restrict__ rw,
                                                          const float* __restrict__ rb) {
    __shared__ float red[8][8];
    __shared__ float smax[8];
    __shared__ float sinv[8];
    __shared__ float wsc[8][8];
    __shared__ float sbias[8];
    __shared__ float ssum[8], ssq[8];
    int bn = blockIdx.x;
    int b = bn >> 10, n = bn & 1023;
    int tid = threadIdx.x;
    int lane = tid & 31, warp = tid >> 5;
    if (tid < 8) { sbias[tid] = rb[tid]; ssum[tid] = 0.f; ssq[tid] = 0.f; }

    float4 r[8];
    #pragma unroll
    for (int h = 0; h < 8; h++)
        r[h] = *(const float4*)&g_S[(((size_t)(b * 8 + h)) * PN + n) * PM + tid * 4];

    float mx[8];
    #pragma unroll
    for (int h = 0; h < 8; h++) {
        mx[h] = fmaxf(fmaxf(r[h].x, r[h].y), fmaxf(r[h].z, r[h].w));
        #pragma unroll
        for (int off = 16; off; off >>= 1)
            mx[h] = fmaxf(mx[h], __shfl_xor_sync(0xffffffffu, mx[h], off));
    }
    if (lane == 0)
        #pragma unroll
        for (int h = 0; h < 8; h++) red[warp][h] = mx[h];
    __syncthreads();
    if (tid < 8) {
        float m2 = red[0][tid];
        #pragma unroll
        for (int w = 1; w < 8; w++) m2 = fmaxf(m2, red[w][tid]);
        smax[tid] = m2;
    }
    __syncthreads();

    float sm[8];
    #pragma unroll
    for (int h = 0; h < 8; h++) {
        float m2 = smax[h];
        r[h].x = __expf(r[h].x - m2);
        r[h].y = __expf(r[h].y - m2);
        r[h].z = __expf(r[h].z - m2);
        r[h].w = __expf(r[h].w - m2);
        sm[h] = r[h].x + r[h].y + r[h].z + r[h].w;
        #pragma unroll
        for (int off = 16; off; off >>= 1)
            sm[h] += __shfl_xor_sync(0xffffffffu, sm[h], off);
    }
    if (lane == 0)
        #pragma unroll
        for (int h = 0; h < 8; h++) red[warp][h] = sm[h];
    __syncthreads();
    if (tid < 8) {
        float t = 0.f;
        #pragma unroll
        for (int w = 0; w < 8; w++) t += red[w][tid];
        sinv[tid] = 1.f / t;
    }
    __syncthreads();
    if (tid < 64) wsc[tid >> 3][tid & 7] = rw[tid] * sinv[tid & 7];
    __syncthreads();

    float ls[8], lq[8];
    #pragma unroll
    for (int g = 0; g < 8; g++) {
        float4 o;
        o.x = sbias[g]; o.y = sbias[g]; o.z = sbias[g]; o.w = sbias[g];
        #pragma unroll
        for (int h = 0; h < 8; h++) {
            float w = wsc[g][h];
            o.x += w * r[h].x; o.y += w * r[h].y;
            o.z += w * r[h].z; o.w += w * r[h].w;
        }
        size_t base = (((size_t)(b * 8 + g)) * PN + n) * PM + tid * 4;
        uint32_t h0, l0, h1, l1;
        split2(o.x, o.y, h0, l0);
        split2(o.z, o.w, h1, l1);
        *(uint2*)&g_ph[base] = make_uint2(h0, h1);
        *(uint2*)&g_pl[base] = make_uint2(l0, l1);
        ls[g] = o.x + o.y + o.z + o.w;
        lq[g] = o.x * o.x + o.y * o.y + o.z * o.z + o.w * o.w;
    }
    #pragma unroll
    for (int g = 0; g < 8; g++) {
        #pragma unroll
        for (int off = 16; off; off >>= 1) {
            ls[g] += __shfl_xor_sync(0xffffffffu, ls[g], off);
            lq[g] += __shfl_xor_sync(0xffffffffu, lq[g], off);
        }
        if (lane == 0) { atomicAdd(&ssum[g], ls[g]); atomicAdd(&ssq[g], lq[g]); }
    }
    __syncthreads();
    if (tid < 8) {
        atomicAdd(&g_stats[tid], (double)ssum[tid]);
        atomicAdd(&g_stats[8 + tid], (double)ssq[tid]);
    }
}

// ---------------------------------------------------------------------------
__global__ void finalize_kernel(const float* __restrict__ gamma,
                                const float* __restrict__ beta) {
    int g = threadIdx.x;
    if (g < 8) {
        double cnt = 8388608.0;
        double mean = g_stats[g] / cnt;
        double var = g_stats[8 + g] / cnt - mean * mean;
        double invstd = rsqrt(var + 1e-5);
        double A = invstd * (double)gamma[g];
        g_norm[g] = (float)A;
        g_norm[8 + g] = (float)((double)beta[g] - mean * A);
    }
}

// ===========================================================================
// av: P@V via cp.async double-buffered chunks (m=64, 16 chunks).
// Epilogue folds BN: oh = Ag*acc + Bg*vsum. attn_out reconstructed from smem.
// ===========================================================================
#define AV_SA 72
#define AV_A_HI 0
#define AV_A_LO 18432
#define AV_B_HI 36864
#define AV_B_LO 50688
#define AV_STAGE 64512
#define AV_SMEM (2 * AV_STAGE)            // 129024

__device__ __forceinline__ void av_stage(uint32_t bufb, int bg, int n0, int m0, int tid) {
    #pragma unroll
    for (int i = 0; i < 4; i++) {
        int idx = tid + i * 256;
        int row = idx >> 3, c = idx & 7;
        size_t src = (size_t)(bg * 1024 + n0 + row) * PM + m0 + c * 8;
        uint32_t so = (uint32_t)(row * AV_SA) * 2 + c * 16;
        CP16(bufb + AV_A_HI + so, g_ph + src);
        CP16(bufb + AV_A_LO + so, g_pl + src);
    }
    #pragma unroll
    for (int i = 0; i < 3; i++) {
        int idx = tid + i * 256;
        int row = idx >> 3, c = idx & 7;
        size_t src = (size_t)bg * PD * PM + (size_t)row * PM + m0 + c * 8;
        uint32_t so = (uint32_t)(row * AV_SA) * 2 + c * 16;
        CP16(bufb + AV_B_HI + so, g_vth + src);
        CP16(bufb + AV_B_LO + so, g_vtl + src);
    }
    CP_COMMIT();
}

__global__ void __launch_bounds__(256) av_mma_kernel(float* __restrict__ attn_out) {
    extern __shared__ char smem[];
    uint32_t sb = smem_u32(smem);
    int tid = threadIdx.x, wid = tid >> 5, lane = tid & 31;
    int nt = blockIdx.x, bg = blockIdx.y;
    int b = bg >> 3, g = bg & 7;
    int n0 = nt * 128;
    float Ag = g_norm[g], Bg = g_norm[8 + g];

    int lr = lane & 7;
    int a_row = lr + ((lane >> 3) & 1) * 8, a_k = (lane >> 4) * 8;
    int b_row = lr + (lane >> 4) * 8,       b_k = ((lane >> 3) & 1) * 8;
    int wr = (wid >> 1) * 32, wc = (wid & 1) * 48;

    av_stage(sb, bg, n0, 0, tid);

    float acc[2][6][4] = {};
    for (int ch = 0; ch < 16; ch++) {
        uint32_t bufb = sb + (ch & 1) * AV_STAGE;
        if (ch + 1 < 16) {
            av_stage(sb + ((ch + 1) & 1) * AV_STAGE, bg, n0, (ch + 1) * 64, tid);
            CP_WAIT1();
        } else {
            CP_WAIT0();
        }
        __syncthreads();

        // attn_out writeback from staged tiles
        int m0 = ch * 64;
        #pragma unroll
        for (int i = 0; i < 8; i++) {
            int idx = tid + i * 256;
            int row = idx >> 4, col4 = (idx & 15) * 4;
            uint32_t so = (uint32_t)(row * AV_SA + col4) * 2;
            uint2 hw = *(uint2*)(smem + (bufb - sb) + AV_A_HI + so);
            uint2 lw = *(uint2*)(smem + (bufb - sb) + AV_A_LO + so);
            float4 v = rec4(hw, lw);
            v.x = v.x * Ag + Bg; v.y = v.y * Ag + Bg;
            v.z = v.z * Ag + Bg; v.w = v.w * Ag + Bg;
            *(float4*)&attn_out[(size_t)(bg * 1024 + n0 + row) * PM + m0 + col4] = v;
        }

        #pragma unroll
        for (int ks = 0; ks < 4; ks++) {
            int k0 = ks * 16;
            uint32_t ah[2][4], al[2][4];
            #pragma unroll
            for (int mf = 0; mf < 2; mf++) {
                uint32_t off = (uint32_t)((wr + mf * 16 + a_row) * AV_SA + k0 + a_k) * 2;
                ldsm4(bufb + AV_A_HI + off, ah[mf]);
                ldsm4(bufb + AV_A_LO + off, al[mf]);
            }
            #pragma unroll
            for (int np = 0; np < 3; np++) {
                uint32_t off = (uint32_t)((wc + np * 16 + b_row) * AV_SA + k0 + b_k) * 2;
                uint32_t bh4[4], bl4[4];
                ldsm4(bufb + AV_B_HI + off, bh4);
                ldsm4(bufb + AV_B_LO + off, bl4);
                #pragma unroll
                for (int mf = 0; mf < 2; mf++)
                    #pragma unroll
                    for (int sub = 0; sub < 2; sub++) {
                        float* d = acc[mf][np * 2 + sub];
                        mma16816(d, ah[mf], &bh4[sub * 2]);
                        mma16816(d, ah[mf], &bl4[sub * 2]);
                        mma16816(d, al[mf], &bh4[sub * 2]);
                    }
            }
        }
        __syncthreads();
    }

    // epilogue: oh = Ag*acc + Bg*vsum; write bf16 hi/lo in (b,n,c) layout
    int r0 = wr + (lane >> 2);
    int cbase = wc + 2 * (lane & 3);
    #pragma unroll
    for (int mf = 0; mf < 2; mf++)
        #pragma unroll
        for (int nf = 0; nf < 6; nf++) {
            int cc = cbase + nf * 8;
            float vs0 = g_vsum[bg * 96 + cc], vs1 = g_vsum[bg * 96 + cc + 1];
            #pragma unroll
            for (int half = 0; half < 2; half++) {
                int rr = r0 + mf * 16 + half * 8;
                float o0 = Ag * acc[mf][nf][half * 2 + 0] + Bg * vs0;
                float o1 = Ag * acc[mf][nf][half * 2 + 1] + Bg * vs1;
                uint32_t hw, lw;
                split2(o0, o1, hw, lw);
                size_t off = (size_t)(b * 1024 + n0 + rr) * PC + g * PD + cc;
                *(uint32_t*)&g_ohh[off] = hw;
                *(uint32_t*)&g_ohl[off] = lw;
            }
        }
}

// ===========================================================================
// proj: 128x128 tile, K=768 in 12 chunks of 64, cp.async double-buffered.
// ===========================================================================
#define PJ_SA 72
#define PJ_A_HI 0
#define PJ_A_LO 18432
#define PJ_B_HI 36864
#define PJ_B_LO 55296
#define PJ_STAGE 73728
#define PJ_SMEM (2 * PJ_STAGE)            // 147456

__device__ __forceinline__ void pj_stage(uint32_t bufb, int r0b, int c0, int kc, int tid) {
    #pragma unroll
    for (int i = 0; i < 4; i++) {
        int idx = tid + i * 256;
        int row = idx >> 3, c = idx & 7;
        size_t sa = (size_t)(r0b + row) * PC + kc + c * 8;
        size_t sw = (size_t)(c0 + row) * PC + kc + c * 8;
        uint32_t so = (uint32_t)(row * PJ_SA) * 2 + c * 16;
        CP16(bufb + PJ_A_HI + so, g_ohh + sa);
        CP16(bufb + PJ_A_LO + so, g_ohl + sa);
        CP16(bufb + PJ_B_HI + so, g_pwh + sw);
        CP16(bufb + PJ_B_LO + so, g_pwl + sw);
    }
    CP_COMMIT();
}

__global__ void __launch_bounds__(256) proj_mma_kernel(const float* __restrict__ pb,
                                                       float* __restrict__ out) {
    extern __shared__ char smem[];
    uint32_t sb = smem_u32(smem);
    int tid = threadIdx.x, wid = tid >> 5, lane = tid & 31;
    int ct = blockIdx.x, rt = blockIdx.y;
    int r0b = rt * 128, c0 = ct * 128;

    int lr = lane & 7;
    int a_row = lr + ((lane >> 3) & 1) * 8, a_k = (lane >> 4) * 8;
    int b_row = lr + (lane >> 4) * 8,       b_k = ((lane >> 3) & 1) * 8;
    int wr = (wid >> 1) * 32, wc = (wid & 1) * 64;

    pj_stage(sb, r0b, c0, 0, tid);

    float acc[2][8][4] = {};
    for (int ch = 0; ch < 12; ch++) {
        uint32_t bufb = sb + (ch & 1) * PJ_STAGE;
        if (ch + 1 < 12) {
            pj_stage(sb + ((ch + 1) & 1) * PJ_STAGE, r0b, c0, (ch + 1) * 64, tid);
            CP_WAIT1();
        } else {
            CP_WAIT0();
        }
        __syncthreads();

        #pragma unroll
        for (int ks = 0; ks < 4; ks++) {
            int k0 = ks * 16;
            uint32_t ah[2][4], al[2][4];
            #pragma unroll
            for (int mf = 0; mf < 2; mf++) {
                uint32_t off = (uint32_t)((wr + mf * 16 + a_row) * PJ_SA + k0 + a_k) * 2;
                ldsm4(bufb + PJ_A_HI + off, ah[mf]);
                ldsm4(bufb + PJ_A_LO + off, al[mf]);
            }
            #pragma unroll
            for (int np = 0; np < 4; np++) {
                uint32_t off = (uint32_t)((wc + np * 16 + b_row) * PJ_SA + k0 + b_k) * 2;
                uint32_t bh4[4], bl4[4];
                ldsm4(bufb + PJ_B_HI + off, bh4);
                ldsm4(bufb + PJ_B_LO + off, bl4);
                #pragma unroll
                for (int mf = 0; mf < 2; mf++)
                    #pragma unroll
                    for (int sub = 0; sub < 2; sub++) {
                        float* d = acc[mf][np * 2 + sub];
                        mma16816(d, ah[mf], &bh4[sub * 2]);
                        mma16816(d, ah[mf], &bl4[sub * 2]);
                        mma16816(d, al[mf], &bh4[sub * 2]);
                    }
            }
        }
        __syncthreads();
    }

    int r0 = wr + (lane >> 2);
    int cbase = wc + 2 * (lane & 3);
    #pragma unroll
    for (int mf = 0; mf < 2; mf++)
        #pragma unroll
        for (int nf = 0; nf < 8; nf++) {
            int rr = r0b + r0 + mf * 16, cc = c0 + cbase + nf * 8;
            float2 o0 = make_float2(acc[mf][nf][0] + pb[cc], acc[mf][nf][1] + pb[cc + 1]);
            float2 o1 = make_float2(acc[mf][nf][2] + pb[cc], acc[mf][nf][3] + pb[cc + 1]);
            *(float2*)&out[(size_t)rr * PC + cc] = o0;
            *(float2*)&out[(size_t)(rr + 8) * PC + cc] = o1;
        }
}

// ---------------------------------------------------------------------------
extern "C" void kernel_launch(void* const* d_in, const int* in_sizes, int n_in,
                              void* d_out, int out_size) {
    const float* x  = (const float*)d_in[0];
    const float* wq = (const float*)d_in[1];
    const float* wk = (const float*)d_in[2];
    const float* wv = (const float*)d_in[3];
    const float* rw = (const float*)d_in[4];
    const float* rb = (const float*)d_in[5];
    const float* gm = (const float*)d_in[6];
    const float* bt = (const float*)d_in[7];
    const float* pw = (const float*)d_in[8];
    const float* pb = (const float*)d_in[9];
    float* out = (float*)d_out;
    float* attn_out = out + (size_t)PB * PN * PC;

    cudaFuncSetAttribute(qk_mma_kernel, cudaFuncAttributeMaxDynamicSharedMemorySize, QK_SMEM);
    cudaFuncSetAttribute(av_mma_kernel, cudaFuncAttributeMaxDynamicSharedMemorySize, AV_SMEM);
    cudaFuncSetAttribute(proj_mma_kernel, cudaFuncAttributeMaxDynamicSharedMemorySize, PJ_SMEM);

    zero_stats_kernel<<<1, 256>>>();
    conv_qkv_kernel<<<PB * PN, 256>>>(x, wq, wk, wv);
    vt_kernel<<<dim3(16, 64), 256>>>();
    pw_split_kernel<<<576, 256>>>(pw);
    qk_mma_kernel<<<dim3(8, 8, 64), 256, QK_SMEM>>>();
    softmax_mix_kernel<<<PB * PN, 256>>>(rw, rb);
    finalize_kernel<<<1, 32>>>(gm, bt);
    av_mma_kernel<<<dim3(8, 64), 256, AV_SMEM>>>(attn_out);
    proj_mma_kernel<<<dim3(6, 64), 256, PJ_SMEM>>>(pb, out);
}